// round 9
// baseline (speedup 1.0000x reference)
#include <cuda_runtime.h>
#include <cuda_bf16.h>
#include <cstdint>

#define NNODES 100000
#define EDGES  1000000
#define INF 64
#define OUTF 64
#define NB 391                 // ceil(100000/256) scan tiles
#define GEMM_BLOCKS 1563       // ceil(100000/64)

typedef unsigned long long ull;

// Scratch (__device__ globals; runtime allocation forbidden).
__device__ int    g_cnt[NNODES];          // zero at entry; re-zeroed by scan_a tail
__device__ int    g_excl[NNODES];
__device__ int    g_rowptr[NNODES + 1];
__device__ int    g_cursor[NNODES];
__device__ int    g_adj[EDGES];
__device__ int    g_bsums[NB];
__device__ float4 g_msg4[(size_t)NNODES * (INF / 4)];   // meaned neighbor feats

// ---------------------------------------------------------------------------
// f32x2 packed-FMA helpers
// ---------------------------------------------------------------------------
__device__ __forceinline__ void fma2(ull& d, ull a, ull b) {
    asm("fma.rn.f32x2 %0, %1, %2, %0;" : "+l"(d) : "l"(a), "l"(b));
}
__device__ __forceinline__ ull dup2(float x) {
    ull r; asm("mov.b64 %0, {%1, %2};" : "=l"(r) : "f"(x), "f"(x)); return r;
}
__device__ __forceinline__ void unpack2(ull v, float& x, float& y) {
    asm("mov.b64 {%0, %1}, %2;" : "=f"(x), "=f"(y) : "l"(v));
}

// ---------------------------------------------------------------------------
// Half-GEMM device routine: acc = srcmat[64 nodes x 64k] @ Wslice^T for one
// 64-node tile. 256 threads, thread tile 4 nodes x 4 outs (f32x2 pairs).
// wofs selects W column block (0 or 64) in W[o*128 + wofs + k].
// ---------------------------------------------------------------------------
__device__ __forceinline__ void half_gemm(const float* __restrict__ srcmat,
                                          const float* __restrict__ W,
                                          int wofs, int gn, int tid,
                                          float* As, float* Ws,
                                          ull acc[2][4]) {
    for (int i = tid; i < 64 * 64; i += 256) {
        int n = i >> 6, k = i & 63;
        int ng = gn + n;
        As[k * 68 + n] = (ng < NNODES) ? srcmat[(size_t)ng * INF + k] : 0.0f;
    }
    for (int i = tid; i < 64 * 64; i += 256) {
        int o = i >> 6, k = i & 63;
        Ws[k * 68 + o] = W[o * 128 + wofs + k];
    }
    __syncthreads();

    int n0 = (tid & 15) * 4;
    int o0 = (tid >> 4) * 4;
#pragma unroll 8
    for (int kk = 0; kk < 64; kk++) {
        ulonglong2 av = *(const ulonglong2*)&As[kk * 68 + n0];   // 4 nodes
        float4 wv = *(const float4*)&Ws[kk * 68 + o0];
        ull ap[2] = {av.x, av.y};
        ull wp[4] = {dup2(wv.x), dup2(wv.y), dup2(wv.z), dup2(wv.w)};
#pragma unroll
        for (int j = 0; j < 2; j++)
#pragma unroll
            for (int oi = 0; oi < 4; oi++)
                fma2(acc[j][oi], ap[j], wp[oi]);
    }
}

// ---------------------------------------------------------------------------
// K1: combined launch — blocks [0, GEMM_BLOCKS) compute partial = h@W1 + b
// into out; blocks [GEMM_BLOCKS, ...) do the degree histogram (4 edges/thread,
// int4 loads -> 4 independent atomics in flight).
// ---------------------------------------------------------------------------
__global__ __launch_bounds__(256)
void k1_hist_partial(const int* __restrict__ dst, int E,
                     const float* __restrict__ h,
                     const float* __restrict__ W,
                     const float* __restrict__ b,
                     float* __restrict__ out) {
    __shared__ float As[64 * 68];
    __shared__ float Ws[64 * 68];
    int tid = threadIdx.x;

    if (blockIdx.x < GEMM_BLOCKS) {
        int gn = blockIdx.x * 64;
        ull acc[2][4];
#pragma unroll
        for (int j = 0; j < 2; j++)
#pragma unroll
            for (int oi = 0; oi < 4; oi++) acc[j][oi] = 0ULL;

        half_gemm(h, W, 0, gn, tid, As, Ws, acc);

        int n0 = (tid & 15) * 4;
        int o0 = (tid >> 4) * 4;
        float4 bv = *(const float4*)&b[o0];
        float bb[4] = {bv.x, bv.y, bv.z, bv.w};
#pragma unroll
        for (int j = 0; j < 2; j++) {
            float x0[4], x1[4];
#pragma unroll
            for (int oi = 0; oi < 4; oi++) unpack2(acc[j][oi], x0[oi], x1[oi]);
            int n = gn + n0 + 2 * j;
            if (n < NNODES) {
                float4 r; r.x = x0[0] + bb[0]; r.y = x0[1] + bb[1];
                r.z = x0[2] + bb[2]; r.w = x0[3] + bb[3];
                *(float4*)&out[(size_t)n * OUTF + o0] = r;
            }
            if (n + 1 < NNODES) {
                float4 r; r.x = x1[0] + bb[0]; r.y = x1[1] + bb[1];
                r.z = x1[2] + bb[2]; r.w = x1[3] + bb[3];
                *(float4*)&out[(size_t)(n + 1) * OUTF + o0] = r;
            }
        }
    } else {
        int hb = blockIdx.x - GEMM_BLOCKS;
        int base = (hb * 256 + tid) * 4;
        if (base + 3 < E) {
            int4 d4 = *(const int4*)(dst + base);
            atomicAdd(&g_cnt[d4.x], 1);
            atomicAdd(&g_cnt[d4.y], 1);
            atomicAdd(&g_cnt[d4.z], 1);
            atomicAdd(&g_cnt[d4.w], 1);
        } else {
            for (int e = base; e < E; e++) atomicAdd(&g_cnt[dst[e]], 1);
        }
    }
}

// ---------------------------------------------------------------------------
// K2: per-block inclusive scan -> block-local exclusive + block totals.
// Tail: zero g_cnt[i] (own element only; race-free) for the next replay.
// ---------------------------------------------------------------------------
__global__ void scan_a_kernel() {
    __shared__ int s[256];
    int tid = threadIdx.x;
    int i = blockIdx.x * 256 + tid;
    int c = (i < NNODES) ? g_cnt[i] : 0;
    s[tid] = c;
    __syncthreads();
#pragma unroll
    for (int off = 1; off < 256; off <<= 1) {
        int v = (tid >= off) ? s[tid - off] : 0;
        __syncthreads();
        s[tid] += v;
        __syncthreads();
    }
    if (i < NNODES) {
        g_excl[i] = s[tid] - c;
        g_cnt[i] = 0;
    }
    if (tid == 255) g_bsums[blockIdx.x] = s[255];
}

// ---------------------------------------------------------------------------
// K3: block bid: base = sum(g_bsums[0..bid-1]); write rowptr + cursor.
// ---------------------------------------------------------------------------
__global__ void scan_c_kernel(int E) {
    __shared__ int r[256];
    int tid = threadIdx.x, bid = blockIdx.x;
    int partial = 0;
    for (int j = tid; j < bid; j += 256) partial += g_bsums[j];
    r[tid] = partial;
    __syncthreads();
#pragma unroll
    for (int off = 128; off > 0; off >>= 1) {
        if (tid < off) r[tid] += r[tid + off];
        __syncthreads();
    }
    int base = r[0];

    int i = bid * 256 + tid;
    if (i < NNODES) {
        int ex = base + g_excl[i];
        g_rowptr[i] = ex;
        g_cursor[i] = ex;
    }
    if (i == 0) g_rowptr[NNODES] = E;
}

// ---------------------------------------------------------------------------
// K4: fill adjacency, 4 edges/thread (int4 loads -> 4 atomics in flight)
// ---------------------------------------------------------------------------
__global__ __launch_bounds__(256)
void fill_kernel(const int* __restrict__ src,
                 const int* __restrict__ dst, int E) {
    int base = (blockIdx.x * blockDim.x + threadIdx.x) * 4;
    if (base + 3 < E) {
        int4 s4 = *(const int4*)(src + base);
        int4 d4 = *(const int4*)(dst + base);
        int p0 = atomicAdd(&g_cursor[d4.x], 1);
        int p1 = atomicAdd(&g_cursor[d4.y], 1);
        int p2 = atomicAdd(&g_cursor[d4.z], 1);
        int p3 = atomicAdd(&g_cursor[d4.w], 1);
        g_adj[p0] = s4.x;
        g_adj[p1] = s4.y;
        g_adj[p2] = s4.z;
        g_adj[p3] = s4.w;
    } else {
        for (int e = base; e < E; e++) {
            int pos = atomicAdd(&g_cursor[dst[e]], 1);
            g_adj[pos] = src[e];
        }
    }
}

// ---------------------------------------------------------------------------
// K5: gather-mean (R8-proven). 1 warp/node; half-warp x float4 rows.
// ---------------------------------------------------------------------------
__global__ __launch_bounds__(256)
void gather_kernel(const float* __restrict__ h) {
    int warp = (blockIdx.x * blockDim.x + threadIdx.x) >> 5;
    int lane = threadIdx.x & 31;
    if (warp >= NNODES) return;
    int beg = g_rowptr[warp];
    int end = g_rowptr[warp + 1];
    int half = lane >> 4;
    int fl   = lane & 15;

    const float4* hp = (const float4*)h;
    float ax = 0.f, ay = 0.f, az = 0.f, aw = 0.f;
#pragma unroll 4
    for (int j = beg + half; j < end; j += 2) {
        int s = g_adj[j];
        float4 v = __ldg(&hp[(size_t)s * 16 + fl]);
        ax += v.x; ay += v.y; az += v.z; aw += v.w;
    }
    ax += __shfl_xor_sync(0xffffffffu, ax, 16);
    ay += __shfl_xor_sync(0xffffffffu, ay, 16);
    az += __shfl_xor_sync(0xffffffffu, az, 16);
    aw += __shfl_xor_sync(0xffffffffu, aw, 16);

    if (half == 0) {
        float inv = 1.0f / fmaxf((float)(end - beg), 1.0f);
        float4 r; r.x = ax * inv; r.y = ay * inv; r.z = az * inv; r.w = aw * inv;
        g_msg4[(size_t)warp * 16 + fl] = r;
    }
}

// ---------------------------------------------------------------------------
// K6: final = relu(partial(out) + msg @ W2)
// ---------------------------------------------------------------------------
__global__ __launch_bounds__(256)
void k6_final(const float* __restrict__ W,
              float* __restrict__ out) {
    __shared__ float As[64 * 68];
    __shared__ float Ws[64 * 68];
    int tid = threadIdx.x;
    int gn = blockIdx.x * 64;

    ull acc[2][4];
#pragma unroll
    for (int j = 0; j < 2; j++)
#pragma unroll
        for (int oi = 0; oi < 4; oi++) acc[j][oi] = 0ULL;

    half_gemm((const float*)g_msg4, W, 64, gn, tid, As, Ws, acc);

    int n0 = (tid & 15) * 4;
    int o0 = (tid >> 4) * 4;
#pragma unroll
    for (int j = 0; j < 2; j++) {
        float x0[4], x1[4];
#pragma unroll
        for (int oi = 0; oi < 4; oi++) unpack2(acc[j][oi], x0[oi], x1[oi]);
        int n = gn + n0 + 2 * j;
        if (n < NNODES) {
            float4 p = *(const float4*)&out[(size_t)n * OUTF + o0];
            float4 r;
            r.x = fmaxf(p.x + x0[0], 0.0f);
            r.y = fmaxf(p.y + x0[1], 0.0f);
            r.z = fmaxf(p.z + x0[2], 0.0f);
            r.w = fmaxf(p.w + x0[3], 0.0f);
            *(float4*)&out[(size_t)n * OUTF + o0] = r;
        }
        if (n + 1 < NNODES) {
            float4 p = *(const float4*)&out[(size_t)(n + 1) * OUTF + o0];
            float4 r;
            r.x = fmaxf(p.x + x1[0], 0.0f);
            r.y = fmaxf(p.y + x1[1], 0.0f);
            r.z = fmaxf(p.z + x1[2], 0.0f);
            r.w = fmaxf(p.w + x1[3], 0.0f);
            *(float4*)&out[(size_t)(n + 1) * OUTF + o0] = r;
        }
    }
}

// ---------------------------------------------------------------------------
// inputs: h [N,64] f32, src [E] i32, dst [E] i32, W [64,128] f32, b [64] f32
// output: [N,64] f32
// ---------------------------------------------------------------------------
extern "C" void kernel_launch(void* const* d_in, const int* in_sizes, int n_in,
                              void* d_out, int out_size) {
    const float* h   = (const float*)d_in[0];
    const int*   src = (const int*)d_in[1];
    const int*   dst = (const int*)d_in[2];
    const float* W   = (const float*)d_in[3];
    const float* b   = (const float*)d_in[4];
    float*       out = (float*)d_out;

    int E = in_sizes[1];
    int hist_blocks = (E + 1023) / 1024;      // 4 edges/thread
    int fill_blocks = (E + 1023) / 1024;

    k1_hist_partial<<<GEMM_BLOCKS + hist_blocks, 256>>>(dst, E, h, W, b, out);
    scan_a_kernel<<<NB, 256>>>();
    scan_c_kernel<<<NB, 256>>>(E);
    fill_kernel<<<fill_blocks, 256>>>(src, dst, E);
    gather_kernel<<<(NNODES * 32 + 255) / 256, 256>>>(h);
    k6_final<<<GEMM_BLOCKS, 256>>>(W, out);
}